// round 6
// baseline (speedup 1.0000x reference)
#include <cuda_runtime.h>
#include <cuda_bf16.h>
#include <cfloat>
#include <cstdint>

// Problem shape (fixed): B=8, N=2048, D=256
#define BATCH 8
#define NDIM  2048
#define DDIM  256

#define TILE 128
#define NT   (NDIM / TILE)               // 16
#define NPAIR ((NT * (NT + 1)) / 2)      // 136 upper-tri tile pairs
#define TOTAL_W (NPAIR * BATCH)          // 1088 work items
#define GRID_SYRK 148                    // persistent: one CTA per SM

// ---------------------------------------------------------------------------
// Device scratch (allocation-free)
// ---------------------------------------------------------------------------
__device__ float g_energy[(size_t)BATCH * NDIM * NDIM];            // 134 MB
// h split into bf16 hi/lo: 8*2048*256 elems = 4,194,304 bf16 = 524288 uint4
__device__ uint4 g_hhi[524288];
__device__ uint4 g_hlo[524288];

// ---------------------------------------------------------------------------
// Kernel 0: split h (fp32) -> h_hi, h_lo (bf16); x ~= hi + lo to ~2^-18 rel
// ---------------------------------------------------------------------------
__global__ void __launch_bounds__(256)
convert_kernel(const float4* __restrict__ h4)
{
    const int base = blockIdx.x * 512 + threadIdx.x;
    #pragma unroll
    for (int i = 0; i < 2; ++i) {
        const int f = base + i * 256;
        const float4 v = h4[f];
        __nv_bfloat16 hx = __float2bfloat16_rn(v.x);
        __nv_bfloat16 hy = __float2bfloat16_rn(v.y);
        __nv_bfloat16 hz = __float2bfloat16_rn(v.z);
        __nv_bfloat16 hw = __float2bfloat16_rn(v.w);
        float lx = v.x - __bfloat162float(hx);
        float ly = v.y - __bfloat162float(hy);
        float lz = v.z - __bfloat162float(hz);
        float lw = v.w - __bfloat162float(hw);
        __nv_bfloat162 hi01 = __nv_bfloat162(hx, hy);
        __nv_bfloat162 hi23 = __nv_bfloat162(hz, hw);
        __nv_bfloat162 lo01 = __floats2bfloat162_rn(lx, ly);
        __nv_bfloat162 lo23 = __floats2bfloat162_rn(lz, lw);
        uint2 uh, ul;
        uh.x = *reinterpret_cast<uint32_t*>(&hi01);
        uh.y = *reinterpret_cast<uint32_t*>(&hi23);
        ul.x = *reinterpret_cast<uint32_t*>(&lo01);
        ul.y = *reinterpret_cast<uint32_t*>(&lo23);
        reinterpret_cast<uint2*>(g_hhi)[f] = uh;
        reinterpret_cast<uint2*>(g_hlo)[f] = ul;
    }
}

// ---------------------------------------------------------------------------
// mma.sync / ldmatrix / cp.async helpers (compute_100-safe, sm_80-era PTX)
// ---------------------------------------------------------------------------
__device__ __forceinline__ uint32_t smem_u32(const void* p) {
    uint32_t a;
    asm("{ .reg .u64 t; cvta.to.shared.u64 t, %1; cvt.u32.u64 %0, t; }"
        : "=r"(a) : "l"(p));
    return a;
}

__device__ __forceinline__ void ldsm_x4(uint32_t* r, uint32_t addr) {
    asm volatile("ldmatrix.sync.aligned.m8n8.x4.shared.b16 {%0,%1,%2,%3}, [%4];"
                 : "=r"(r[0]), "=r"(r[1]), "=r"(r[2]), "=r"(r[3]) : "r"(addr));
}

__device__ __forceinline__ void mma16816(float* d, const uint32_t* a,
                                         const uint32_t* b) {
    asm volatile("mma.sync.aligned.m16n8k16.row.col.f32.bf16.bf16.f32 "
                 "{%0,%1,%2,%3}, {%4,%5,%6,%7}, {%8,%9}, {%0,%1,%2,%3};"
                 : "+f"(d[0]), "+f"(d[1]), "+f"(d[2]), "+f"(d[3])
                 : "r"(a[0]), "r"(a[1]), "r"(a[2]), "r"(a[3]),
                   "r"(b[0]), "r"(b[1]));
}

__device__ __forceinline__ void cp_async16(uint32_t smem_dst, const void* gptr) {
    asm volatile("cp.async.cg.shared.global [%0], [%1], 16;\n"
                 :: "r"(smem_dst), "l"(__cvta_generic_to_global(gptr))
                 : "memory");
}
#define CP_COMMIT() asm volatile("cp.async.commit_group;\n" ::: "memory")
#define CP_WAIT(n)  asm volatile("cp.async.wait_group %0;\n" :: "n"(n) : "memory")

// Chunk-XOR swizzle for 64B rows (4 x 16B chunks): conflict-free ldmatrix
__device__ __forceinline__ uint32_t swz(int row, int kc) {
    return (uint32_t)(row * 64 + ((kc ^ ((row >> 1) & 3)) << 4));
}

// ---------------------------------------------------------------------------
// Kernel 1: persistent SYRK energy[b]=h[b]*h[b]^T, split-bf16 3-MMA.
// Grid = 148 CTAs; each walks work items w = bid + k*148 (w < 1088).
// 3-stage cp.async ring pipelined ACROSS pair boundaries: epilogue of pair p
// overlaps the loads of pair p+1. One barrier per K-chunk.
// ---------------------------------------------------------------------------
#define STAGE_BYTES 32768           // 4 arrays x 128 rows x 64B
#define ARR_BYTES   8192
#define SD_OFF      (3 * STAGE_BYTES)                    // 98304
#define SYRK_SMEM   (SD_OFF + 128 * 129 * 4)             // 164352

// decode work id -> batch, tile-row/col bases
__device__ __forceinline__ void decode_w(int w, int& bb, int& a_base, int& b_base)
{
    bb = w / NPAIR;
    int p = w - bb * NPAIR;
    int ti = 0;
    while (p >= (NT - ti)) { p -= (NT - ti); ++ti; }
    a_base = ti * TILE;
    b_base = (ti + p) * TILE;
}

// issue the 2048 cp.async (8 per thread) for chunk q (global chunk stream)
__device__ __forceinline__ void load_chunk_q(uint32_t smem_base, int bid,
                                             int q, int tid)
{
    const int p_idx = q >> 3;
    const int w = bid + p_idx * GRID_SYRK;
    const int c = q & 7;
    int bb, a_base, b_base;
    decode_w(w, bb, a_base, b_base);
    const int batch4 = bb * 65536;
    const uint32_t sm_stage = smem_base + (uint32_t)(q % 3) * STAGE_BYTES;

    #pragma unroll
    for (int i = 0; i < 8; ++i) {
        const int id  = tid + i * 256;      // 0..2047
        const int arr = id >> 9;            // 0=Ahi 1=Alo 2=Bhi 3=Blo
        const int cid = id & 511;
        const int row = cid >> 2;
        const int ch  = cid & 3;
        const uint32_t dst = sm_stage + arr * ARR_BYTES + swz(row, ch);
        const int grow = ((arr < 2) ? a_base : b_base) + row;
        const uint4* src = ((arr & 1) ? g_hlo : g_hhi)
                           + batch4 + grow * 32 + c * 4 + ch;
        cp_async16(dst, src);
    }
}

__global__ void __launch_bounds__(256, 1)
syrk_mma_kernel()
{
    extern __shared__ char smc[];
    const uint32_t smem_base = smem_u32(smc);
    float* sD = reinterpret_cast<float*>(smc + SD_OFF);
    const int tid  = threadIdx.x;
    const int wid  = tid >> 5;
    const int lane = tid & 31;
    const int bid  = blockIdx.x;

    const int nw = (TOTAL_W - bid + GRID_SYRK - 1) / GRID_SYRK;  // 7 or 8
    const int total_q = nw * 8;

    const int wm = (wid & 3) * 32;          // warp row origin in tile
    const int wn = (wid >> 2) * 64;         // warp col origin in tile

    // ldmatrix per-lane address components
    const int r8   = lane & 7;
    const int a_dr = (lane & 8);
    const int a_dk = (lane >> 4);
    const int b_dr = (lane & 16) >> 1;
    const int b_dk = (lane >> 3) & 1;

    float acc[2][8][4];
    #pragma unroll
    for (int mt = 0; mt < 2; ++mt)
        #pragma unroll
        for (int nt = 0; nt < 8; ++nt)
            #pragma unroll
            for (int q = 0; q < 4; ++q)
                acc[mt][nt][q] = 0.0f;

    // prime 2 chunks
    load_chunk_q(smem_base, bid, 0, tid);
    CP_COMMIT();
    if (total_q > 1) load_chunk_q(smem_base, bid, 1, tid);
    CP_COMMIT();

    #pragma unroll 1
    for (int q = 0; q < total_q; ++q) {
        CP_WAIT(1);
        __syncthreads();

        const uint32_t sb  = smem_base + (uint32_t)(q % 3) * STAGE_BYTES;
        const uint32_t sAh = sb;
        const uint32_t sAl = sb + ARR_BYTES;
        const uint32_t sBh = sb + 2 * ARR_BYTES;
        const uint32_t sBl = sb + 3 * ARR_BYTES;

        // issue loads for chunk q+2 (possibly next pair) — overlaps compute
        if (q + 2 < total_q) load_chunk_q(smem_base, bid, q + 2, tid);
        CP_COMMIT();   // uniform: empty group when no loads issued

        #pragma unroll
        for (int ks = 0; ks < 2; ++ks) {
            uint32_t ahi[2][4], alo[2][4], bf[4][4];

            #pragma unroll
            for (int mt = 0; mt < 2; ++mt) {
                const int row = wm + mt * 16 + a_dr + r8;
                const int kc  = 2 * ks + a_dk;
                const uint32_t off = swz(row, kc);
                ldsm_x4(ahi[mt], sAh + off);
                ldsm_x4(alo[mt], sAl + off);
            }
            #pragma unroll
            for (int np = 0; np < 4; ++np) {
                const int row = wn + np * 16 + b_dr + r8;
                const int kc  = 2 * ks + b_dk;
                ldsm_x4(bf[np], sBh + swz(row, kc));
            }
            // hh + lh
            #pragma unroll
            for (int mt = 0; mt < 2; ++mt)
                #pragma unroll
                for (int np = 0; np < 4; ++np) {
                    mma16816(acc[mt][2 * np],     ahi[mt], &bf[np][0]);
                    mma16816(acc[mt][2 * np + 1], ahi[mt], &bf[np][2]);
                    mma16816(acc[mt][2 * np],     alo[mt], &bf[np][0]);
                    mma16816(acc[mt][2 * np + 1], alo[mt], &bf[np][2]);
                }
            // B lo over same regs
            #pragma unroll
            for (int np = 0; np < 4; ++np) {
                const int row = wn + np * 16 + b_dr + r8;
                const int kc  = 2 * ks + b_dk;
                ldsm_x4(bf[np], sBl + swz(row, kc));
            }
            // hl
            #pragma unroll
            for (int mt = 0; mt < 2; ++mt)
                #pragma unroll
                for (int np = 0; np < 4; ++np) {
                    mma16816(acc[mt][2 * np],     ahi[mt], &bf[np][0]);
                    mma16816(acc[mt][2 * np + 1], ahi[mt], &bf[np][2]);
                }
        }

        if ((q & 7) == 7) {
            // ---------------- epilogue for finished pair ----------------
            const int w = bid + (q >> 3) * GRID_SYRK;
            int bb, a_base, b_base;
            decode_w(w, bb, a_base, b_base);

            // acc -> sD[128][129]
            {
                const int rq = lane >> 2;
                const int cq = (lane & 3) * 2;
                #pragma unroll
                for (int mt = 0; mt < 2; ++mt) {
                    const int r0 = wm + mt * 16 + rq;
                    #pragma unroll
                    for (int nt = 0; nt < 8; ++nt) {
                        const int cc = wn + nt * 8 + cq;
                        sD[r0 * 129 + cc]           = acc[mt][nt][0];
                        sD[r0 * 129 + cc + 1]       = acc[mt][nt][1];
                        sD[(r0 + 8) * 129 + cc]     = acc[mt][nt][2];
                        sD[(r0 + 8) * 129 + cc + 1] = acc[mt][nt][3];
                    }
                }
            }
            __syncthreads();

            float* eb = g_energy + (size_t)bb * NDIM * NDIM;

            // direct tile: coalesced float4 streaming stores
            #pragma unroll 4
            for (int i = 0; i < 16; ++i) {
                const int idx = tid + i * 256;
                const int r  = idx >> 5;
                const int c4 = (idx & 31) * 4;
                float4 v = make_float4(sD[r * 129 + c4 + 0], sD[r * 129 + c4 + 1],
                                       sD[r * 129 + c4 + 2], sD[r * 129 + c4 + 3]);
                __stcs(reinterpret_cast<float4*>(
                    &eb[(size_t)(a_base + r) * NDIM + b_base + c4]), v);
            }

            // mirror tile (transpose through smem), skip diagonal
            if (a_base != b_base) {
                #pragma unroll 4
                for (int i = 0; i < 16; ++i) {
                    const int idx = tid + i * 256;
                    const int r2 = idx >> 5;
                    const int c4 = (idx & 31) * 4;
                    float4 v = make_float4(sD[(c4 + 0) * 129 + r2],
                                           sD[(c4 + 1) * 129 + r2],
                                           sD[(c4 + 2) * 129 + r2],
                                           sD[(c4 + 3) * 129 + r2]);
                    __stcs(reinterpret_cast<float4*>(
                        &eb[(size_t)(b_base + r2) * NDIM + a_base + c4]), v);
                }
            }

            // reset accumulators for next pair
            #pragma unroll
            for (int mt = 0; mt < 2; ++mt)
                #pragma unroll
                for (int nt = 0; nt < 8; ++nt)
                    #pragma unroll
                    for (int qq = 0; qq < 4; ++qq)
                        acc[mt][nt][qq] = 0.0f;
            // NOTE: no end barrier needed: next sD write is >=8 chunk-barriers away
        }
    }
    CP_WAIT(0);   // drain any tail cp.async before CTA exit
}

// ---------------------------------------------------------------------------
// Kernel 2: fused rowmax + mask + stable softmax. Register-resident row,
// warp-shuffle reductions, streaming cache hints (read/write-once data).
// ---------------------------------------------------------------------------
__device__ __forceinline__ float blk_reduce_max(float v, float* red,
                                                int wid, int lid)
{
    #pragma unroll
    for (int off = 16; off > 0; off >>= 1)
        v = fmaxf(v, __shfl_xor_sync(0xFFFFFFFFu, v, off));
    if (lid == 0) red[wid] = v;
    __syncthreads();
    float m = red[0];
    #pragma unroll
    for (int i = 1; i < 8; ++i) m = fmaxf(m, red[i]);
    __syncthreads();
    return m;
}

__device__ __forceinline__ float blk_reduce_sum(float v, float* red,
                                                int wid, int lid)
{
    #pragma unroll
    for (int off = 16; off > 0; off >>= 1)
        v += __shfl_xor_sync(0xFFFFFFFFu, v, off);
    if (lid == 0) red[wid] = v;
    __syncthreads();
    float s = red[0];
    #pragma unroll
    for (int i = 1; i < 8; ++i) s += red[i];
    __syncthreads();
    return s;
}

__global__ void __launch_bounds__(256)
softmax_kernel(const float* __restrict__ adj, float* __restrict__ out)
{
    const size_t row = blockIdx.x;
    const float4* e4 = reinterpret_cast<const float4*>(g_energy + row * NDIM);
    const float4* a4 = reinterpret_cast<const float4*>(adj + row * NDIM);
    float4*       o4 = reinterpret_cast<float4*>(out + row * NDIM);

    __shared__ float red[8];
    const int tid = threadIdx.x;
    const int wid = tid >> 5;
    const int lid = tid & 31;

    float4 e0 = __ldcs(e4 + tid),  e1 = __ldcs(e4 + tid + 256);
    float4 a0 = __ldcs(a4 + tid),  a1 = __ldcs(a4 + tid + 256);

    float m = fmaxf(fmaxf(fmaxf(e0.x, e0.y), fmaxf(e0.z, e0.w)),
                    fmaxf(fmaxf(e1.x, e1.y), fmaxf(e1.z, e1.w)));
    const float m1 = blk_reduce_max(m, red, wid, lid);

    float t[8];
    t[0] = (m1 - e0.x) * a0.x;  t[1] = (m1 - e0.y) * a0.y;
    t[2] = (m1 - e0.z) * a0.z;  t[3] = (m1 - e0.w) * a0.w;
    t[4] = (m1 - e1.x) * a1.x;  t[5] = (m1 - e1.y) * a1.y;
    t[6] = (m1 - e1.z) * a1.z;  t[7] = (m1 - e1.w) * a1.w;

    float m2l = t[0];
    #pragma unroll
    for (int i = 1; i < 8; ++i) m2l = fmaxf(m2l, t[i]);
    const float m2 = blk_reduce_max(m2l, red, wid, lid);

    float pv[8], s = 0.0f;
    #pragma unroll
    for (int i = 0; i < 8; ++i) { pv[i] = __expf(t[i] - m2); s += pv[i]; }
    const float sum = blk_reduce_sum(s, red, wid, lid);

    const float inv = 1.0f / sum;
    __stcs(o4 + tid,
           make_float4(pv[0] * inv, pv[1] * inv, pv[2] * inv, pv[3] * inv));
    __stcs(o4 + tid + 256,
           make_float4(pv[4] * inv, pv[5] * inv, pv[6] * inv, pv[7] * inv));
}

// ---------------------------------------------------------------------------
extern "C" void kernel_launch(void* const* d_in, const int* in_sizes, int n_in,
                              void* d_out, int out_size)
{
    const float* h   = (const float*)d_in[0];   // [8, 2048, 256]
    const float* adj = (const float*)d_in[1];   // [8, 2048, 2048]
    float*       out = (float*)d_out;           // [8, 2048, 2048]
    (void)in_sizes; (void)n_in; (void)out_size;

    // Unconditional (no static guard). Host-side, idempotent, capture-safe.
    cudaFuncSetAttribute(syrk_mma_kernel,
                         cudaFuncAttributeMaxDynamicSharedMemorySize,
                         SYRK_SMEM);

    convert_kernel<<<2048, 256>>>(reinterpret_cast<const float4*>(h));

    syrk_mma_kernel<<<GRID_SYRK, 256, SYRK_SMEM>>>();

    softmax_kernel<<<BATCH * NDIM, 256>>>(adj, out);
}

// round 8
// speedup vs baseline: 1.1693x; 1.1693x over previous
#include <cuda_runtime.h>
#include <cuda_bf16.h>
#include <cfloat>
#include <cstdint>

// Problem shape (fixed): B=8, N=2048, D=256
#define BATCH 8
#define NDIM  2048
#define DDIM  256

#define TILE 128
#define NT   (NDIM / TILE)               // 16
#define NPAIR ((NT * (NT + 1)) / 2)      // 136 upper-tri tile pairs

// ---------------------------------------------------------------------------
// Device scratch (allocation-free)
// ---------------------------------------------------------------------------
__device__ float g_energy[(size_t)BATCH * NDIM * NDIM];            // 134 MB
// h split into bf16 hi/lo: 8*2048*256 elems = 4,194,304 bf16 = 524288 uint4
__device__ uint4 g_hhi[524288];
__device__ uint4 g_hlo[524288];

// ---------------------------------------------------------------------------
// Kernel 0: split h (fp32) -> h_hi, h_lo (bf16); x ~= hi + lo to ~2^-18 rel
// ---------------------------------------------------------------------------
__global__ void __launch_bounds__(256)
convert_kernel(const float4* __restrict__ h4)
{
    const int base = blockIdx.x * 512 + threadIdx.x;
    #pragma unroll
    for (int i = 0; i < 2; ++i) {
        const int f = base + i * 256;
        const float4 v = h4[f];
        __nv_bfloat16 hx = __float2bfloat16_rn(v.x);
        __nv_bfloat16 hy = __float2bfloat16_rn(v.y);
        __nv_bfloat16 hz = __float2bfloat16_rn(v.z);
        __nv_bfloat16 hw = __float2bfloat16_rn(v.w);
        float lx = v.x - __bfloat162float(hx);
        float ly = v.y - __bfloat162float(hy);
        float lz = v.z - __bfloat162float(hz);
        float lw = v.w - __bfloat162float(hw);
        __nv_bfloat162 hi01 = __nv_bfloat162(hx, hy);
        __nv_bfloat162 hi23 = __nv_bfloat162(hz, hw);
        __nv_bfloat162 lo01 = __floats2bfloat162_rn(lx, ly);
        __nv_bfloat162 lo23 = __floats2bfloat162_rn(lz, lw);
        uint2 uh, ul;
        uh.x = *reinterpret_cast<uint32_t*>(&hi01);
        uh.y = *reinterpret_cast<uint32_t*>(&hi23);
        ul.x = *reinterpret_cast<uint32_t*>(&lo01);
        ul.y = *reinterpret_cast<uint32_t*>(&lo23);
        reinterpret_cast<uint2*>(g_hhi)[f] = uh;
        reinterpret_cast<uint2*>(g_hlo)[f] = ul;
    }
}

// ---------------------------------------------------------------------------
// mma.sync / ldmatrix / cp.async helpers (compute_100-safe, sm_80-era PTX)
// ---------------------------------------------------------------------------
__device__ __forceinline__ uint32_t smem_u32(const void* p) {
    uint32_t a;
    asm("{ .reg .u64 t; cvta.to.shared.u64 t, %1; cvt.u32.u64 %0, t; }"
        : "=r"(a) : "l"(p));
    return a;
}

__device__ __forceinline__ void ldsm_x4(uint32_t* r, uint32_t addr) {
    asm volatile("ldmatrix.sync.aligned.m8n8.x4.shared.b16 {%0,%1,%2,%3}, [%4];"
                 : "=r"(r[0]), "=r"(r[1]), "=r"(r[2]), "=r"(r[3]) : "r"(addr));
}

__device__ __forceinline__ void mma16816(float* d, const uint32_t* a,
                                         const uint32_t* b) {
    asm volatile("mma.sync.aligned.m16n8k16.row.col.f32.bf16.bf16.f32 "
                 "{%0,%1,%2,%3}, {%4,%5,%6,%7}, {%8,%9}, {%0,%1,%2,%3};"
                 : "+f"(d[0]), "+f"(d[1]), "+f"(d[2]), "+f"(d[3])
                 : "r"(a[0]), "r"(a[1]), "r"(a[2]), "r"(a[3]),
                   "r"(b[0]), "r"(b[1]));
}

__device__ __forceinline__ void cp_async16(uint32_t smem_dst, const void* gptr) {
    asm volatile("cp.async.cg.shared.global [%0], [%1], 16;\n"
                 :: "r"(smem_dst), "l"(__cvta_generic_to_global(gptr))
                 : "memory");
}
#define CP_COMMIT() asm volatile("cp.async.commit_group;\n" ::: "memory")
#define CP_WAIT(n)  asm volatile("cp.async.wait_group %0;\n" :: "n"(n) : "memory")

// Chunk-XOR swizzle for 64B rows (4 x 16B chunks): conflict-free ldmatrix
__device__ __forceinline__ uint32_t swz(int row, int kc) {
    return (uint32_t)(row * 64 + ((kc ^ ((row >> 1) & 3)) << 4));
}

// ---------------------------------------------------------------------------
// Kernel 1: SYRK energy[b] = h[b]*h[b]^T via split-bf16 3-MMA (mma.sync).
// 128x128 CTA tile, 8 warps of 32x64. K chunk = 32, double-buffered cp.async.
// __launch_bounds__(256, 2): <=128 regs -> 2 CTAs/SM so one CTA's mainloop
// hides the other's epilogue + prologue.
// ---------------------------------------------------------------------------
#define STAGE_BYTES 32768           // 4 arrays x 128 rows x 64B
#define ARR_BYTES   8192
#define SYRK_SMEM   66048           // max(2*STAGE, 128*129*4 epilogue)

__device__ __forceinline__ void load_stage(uint32_t sm_stage, int a_row0,
                                           int b_row0, int c, int tid,
                                           int batch4)
{
    #pragma unroll
    for (int i = 0; i < 8; ++i) {
        const int id  = tid + i * 256;      // 0..2047
        const int arr = id >> 9;            // 0=Ahi 1=Alo 2=Bhi 3=Blo
        const int cid = id & 511;
        const int row = cid >> 2;
        const int ch  = cid & 3;
        const uint32_t dst = sm_stage + arr * ARR_BYTES + swz(row, ch);
        const int grow = ((arr < 2) ? a_row0 : b_row0) + row;
        const uint4* src = ((arr & 1) ? g_hlo : g_hhi)
                           + batch4 + grow * 32 + c * 4 + ch;
        cp_async16(dst, src);
    }
}

__global__ void __launch_bounds__(256, 2)
syrk_mma_kernel()
{
    extern __shared__ char smc[];
    const uint32_t smem_base = smem_u32(smc);
    const int tid  = threadIdx.x;
    const int wid  = tid >> 5;
    const int lane = tid & 31;
    const int b    = blockIdx.y;

    // decode (ti, tj), ti <= tj
    int p = blockIdx.x;
    int ti = 0;
    while (p >= (NT - ti)) { p -= (NT - ti); ++ti; }
    const int tj = ti + p;

    const int a_base = ti * TILE;
    const int b_base = tj * TILE;
    const int batch4 = b * 65536;           // uint4 offset of batch

    const int wm = (wid & 3) * 32;          // warp row origin in tile
    const int wn = (wid >> 2) * 64;         // warp col origin in tile

    float acc[2][8][4];
    #pragma unroll
    for (int mt = 0; mt < 2; ++mt)
        #pragma unroll
        for (int nt = 0; nt < 8; ++nt)
            #pragma unroll
            for (int q = 0; q < 4; ++q)
                acc[mt][nt][q] = 0.0f;

    // prime two stages
    load_stage(smem_base,               a_base, b_base, 0, tid, batch4);
    CP_COMMIT();
    load_stage(smem_base + STAGE_BYTES, a_base, b_base, 1, tid, batch4);
    CP_COMMIT();

    // ldmatrix per-lane address components
    const int r8   = lane & 7;
    const int a_dr = (lane & 8);            // (grp&1)<<3
    const int a_dk = (lane >> 4);           // grp>>1
    const int b_dr = (lane & 16) >> 1;      // (grp>>1)<<3
    const int b_dk = (lane >> 3) & 1;       // grp&1

    #pragma unroll 1
    for (int c = 0; c < 8; ++c) {
        if (c < 7) { CP_WAIT(1); } else { CP_WAIT(0); }
        __syncthreads();

        const uint32_t sb  = smem_base + (uint32_t)(c & 1) * STAGE_BYTES;
        const uint32_t sAh = sb;
        const uint32_t sAl = sb + ARR_BYTES;
        const uint32_t sBh = sb + 2 * ARR_BYTES;
        const uint32_t sBl = sb + 3 * ARR_BYTES;

        #pragma unroll
        for (int ks = 0; ks < 2; ++ks) {
            uint32_t ahi[2][4], alo[2][4], bf[4][4];

            #pragma unroll
            for (int mt = 0; mt < 2; ++mt) {
                const int row = wm + mt * 16 + a_dr + r8;
                const int kc  = 2 * ks + a_dk;
                const uint32_t off = swz(row, kc);
                ldsm_x4(ahi[mt], sAh + off);
                ldsm_x4(alo[mt], sAl + off);
            }
            #pragma unroll
            for (int np = 0; np < 4; ++np) {
                const int row = wn + np * 16 + b_dr + r8;
                const int kc  = 2 * ks + b_dk;
                ldsm_x4(bf[np], sBh + swz(row, kc));
            }
            // hh + lh
            #pragma unroll
            for (int mt = 0; mt < 2; ++mt)
                #pragma unroll
                for (int np = 0; np < 4; ++np) {
                    mma16816(acc[mt][2 * np],     ahi[mt], &bf[np][0]);
                    mma16816(acc[mt][2 * np + 1], ahi[mt], &bf[np][2]);
                    mma16816(acc[mt][2 * np],     alo[mt], &bf[np][0]);
                    mma16816(acc[mt][2 * np + 1], alo[mt], &bf[np][2]);
                }
            // B lo over same regs
            #pragma unroll
            for (int np = 0; np < 4; ++np) {
                const int row = wn + np * 16 + b_dr + r8;
                const int kc  = 2 * ks + b_dk;
                ldsm_x4(bf[np], sBl + swz(row, kc));
            }
            // hl
            #pragma unroll
            for (int mt = 0; mt < 2; ++mt)
                #pragma unroll
                for (int np = 0; np < 4; ++np) {
                    mma16816(acc[mt][2 * np],     ahi[mt], &bf[np][0]);
                    mma16816(acc[mt][2 * np + 1], ahi[mt], &bf[np][2]);
                }
        }

        __syncthreads();   // all warps done reading this stage
        if (c + 2 < 8) {
            load_stage(smem_base + (uint32_t)(c & 1) * STAGE_BYTES,
                       a_base, b_base, c + 2, tid, batch4);
            CP_COMMIT();
        }
    }

    // ---------------- epilogue: acc -> sD[128][129] -> gmem ----------------
    float* sD = reinterpret_cast<float*>(smc);
    {
        const int rq = lane >> 2;           // 0..7
        const int cq = (lane & 3) * 2;
        #pragma unroll
        for (int mt = 0; mt < 2; ++mt) {
            const int r0 = wm + mt * 16 + rq;
            #pragma unroll
            for (int nt = 0; nt < 8; ++nt) {
                const int cc = wn + nt * 8 + cq;
                sD[r0 * 129 + cc]           = acc[mt][nt][0];
                sD[r0 * 129 + cc + 1]       = acc[mt][nt][1];
                sD[(r0 + 8) * 129 + cc]     = acc[mt][nt][2];
                sD[(r0 + 8) * 129 + cc + 1] = acc[mt][nt][3];
            }
        }
    }
    __syncthreads();

    float* eb = g_energy + (size_t)b * NDIM * NDIM;

    // direct tile: fully coalesced float4 streaming stores
    #pragma unroll 4
    for (int i = 0; i < 16; ++i) {
        const int idx = tid + i * 256;
        const int r  = idx >> 5;
        const int c4 = (idx & 31) * 4;
        float4 v = make_float4(sD[r * 129 + c4 + 0], sD[r * 129 + c4 + 1],
                               sD[r * 129 + c4 + 2], sD[r * 129 + c4 + 3]);
        __stcs(reinterpret_cast<float4*>(
            &eb[(size_t)(a_base + r) * NDIM + b_base + c4]), v);
    }

    // mirror tile (transpose through smem), skip diagonal
    if (ti != tj) {
        #pragma unroll 4
        for (int i = 0; i < 16; ++i) {
            const int idx = tid + i * 256;
            const int r2 = idx >> 5;
            const int c4 = (idx & 31) * 4;
            float4 v = make_float4(sD[(c4 + 0) * 129 + r2], sD[(c4 + 1) * 129 + r2],
                                   sD[(c4 + 2) * 129 + r2], sD[(c4 + 3) * 129 + r2]);
            __stcs(reinterpret_cast<float4*>(
                &eb[(size_t)(b_base + r2) * NDIM + a_base + c4]), v);
        }
    }
}

// ---------------------------------------------------------------------------
// Kernel 2: fused rowmax + mask + stable softmax. Register-resident row,
// warp-shuffle reductions, streaming cache hints (read/write-once data).
// ---------------------------------------------------------------------------
__device__ __forceinline__ float blk_reduce_max(float v, float* red,
                                                int wid, int lid)
{
    #pragma unroll
    for (int off = 16; off > 0; off >>= 1)
        v = fmaxf(v, __shfl_xor_sync(0xFFFFFFFFu, v, off));
    if (lid == 0) red[wid] = v;
    __syncthreads();
    float m = red[0];
    #pragma unroll
    for (int i = 1; i < 8; ++i) m = fmaxf(m, red[i]);
    __syncthreads();
    return m;
}

__device__ __forceinline__ float blk_reduce_sum(float v, float* red,
                                                int wid, int lid)
{
    #pragma unroll
    for (int off = 16; off > 0; off >>= 1)
        v += __shfl_xor_sync(0xFFFFFFFFu, v, off);
    if (lid == 0) red[wid] = v;
    __syncthreads();
    float s = red[0];
    #pragma unroll
    for (int i = 1; i < 8; ++i) s += red[i];
    __syncthreads();
    return s;
}

__global__ void __launch_bounds__(256)
softmax_kernel(const float* __restrict__ adj, float* __restrict__ out)
{
    const size_t row = blockIdx.x;
    const float4* e4 = reinterpret_cast<const float4*>(g_energy + row * NDIM);
    const float4* a4 = reinterpret_cast<const float4*>(adj + row * NDIM);
    float4*       o4 = reinterpret_cast<float4*>(out + row * NDIM);

    __shared__ float red[8];
    const int tid = threadIdx.x;
    const int wid = tid >> 5;
    const int lid = tid & 31;

    float4 e0 = __ldcs(e4 + tid),  e1 = __ldcs(e4 + tid + 256);
    float4 a0 = __ldcs(a4 + tid),  a1 = __ldcs(a4 + tid + 256);

    float m = fmaxf(fmaxf(fmaxf(e0.x, e0.y), fmaxf(e0.z, e0.w)),
                    fmaxf(fmaxf(e1.x, e1.y), fmaxf(e1.z, e1.w)));
    const float m1 = blk_reduce_max(m, red, wid, lid);

    float t[8];
    t[0] = (m1 - e0.x) * a0.x;  t[1] = (m1 - e0.y) * a0.y;
    t[2] = (m1 - e0.z) * a0.z;  t[3] = (m1 - e0.w) * a0.w;
    t[4] = (m1 - e1.x) * a1.x;  t[5] = (m1 - e1.y) * a1.y;
    t[6] = (m1 - e1.z) * a1.z;  t[7] = (m1 - e1.w) * a1.w;

    float m2l = t[0];
    #pragma unroll
    for (int i = 1; i < 8; ++i) m2l = fmaxf(m2l, t[i]);
    const float m2 = blk_reduce_max(m2l, red, wid, lid);

    float pv[8], s = 0.0f;
    #pragma unroll
    for (int i = 0; i < 8; ++i) { pv[i] = __expf(t[i] - m2); s += pv[i]; }
    const float sum = blk_reduce_sum(s, red, wid, lid);

    const float inv = 1.0f / sum;
    __stcs(o4 + tid,
           make_float4(pv[0] * inv, pv[1] * inv, pv[2] * inv, pv[3] * inv));
    __stcs(o4 + tid + 256,
           make_float4(pv[4] * inv, pv[5] * inv, pv[6] * inv, pv[7] * inv));
}

// ---------------------------------------------------------------------------
extern "C" void kernel_launch(void* const* d_in, const int* in_sizes, int n_in,
                              void* d_out, int out_size)
{
    const float* h   = (const float*)d_in[0];   // [8, 2048, 256]
    const float* adj = (const float*)d_in[1];   // [8, 2048, 2048]
    float*       out = (float*)d_out;           // [8, 2048, 2048]
    (void)in_sizes; (void)n_in; (void)out_size;

    // Unconditional (no static guard). Host-side, idempotent, capture-safe.
    cudaFuncSetAttribute(syrk_mma_kernel,
                         cudaFuncAttributeMaxDynamicSharedMemorySize,
                         SYRK_SMEM);

    convert_kernel<<<2048, 256>>>(reinterpret_cast<const float4*>(h));

    dim3 g1(NPAIR, BATCH);
    syrk_mma_kernel<<<g1, 256, SYRK_SMEM>>>();

    softmax_kernel<<<BATCH * NDIM, 256>>>(adj, out);
}